// round 14
// baseline (speedup 1.0000x reference)
#include <cuda_runtime.h>

// Pitch loss — final form (R8 shape, micro-trimmed).
//
// Structure: memset node zeroes the scalar output, then ONE retire-fast
// kernel. Grid 32 x 256 = 256 warps; each warp handles 4 contiguous 32-frame
// notes via 8-lane groups. Lane sub (0..7) of group grp (0..3) loads ONE
// float4 per track (the warp spans 512B contiguous per track -> fully
// coalesced LDG.128), 3 width-8 shuffles reduce the gen-t difference, and the
// group leader tests |sum| > 0.5*len (threshold precomputed early; no
// division anywhere -- inv_n arrives as a kernel argument fixed at graph
// capture). On a hit the leader fires atomicAdd(out, inv_n) with the return
// UNUSED -> compiles to REDG (no-return reduction): no L2 round trip on any
// warp's critical path, warps retire immediately. No __syncthreads, no
// device scratch, no completion detection (measured: every in-kernel
// completion scheme costs >= the node tax it would save).
//
// Determinism: every contribution is exactly 2^-10 and all partial sums
// m/1024 (m <= 1024) are exactly representable in fp32 -> the accumulation
// is order-independent and bit-exact across graph replays. The memset node
// is in the same stream, so it is ordered before the kernel's reductions.
__global__ void __launch_bounds__(256, 1)
pitch_loss_kernel(const float* __restrict__ gen_f0,
                  const float* __restrict__ t_f0,
                  const int*   __restrict__ onset,
                  const int*   __restrict__ offset,
                  float*       __restrict__ out,
                  int N, float inv_n) {
    const int lane  = threadIdx.x & 31;
    const int sub   = lane & 7;                       // float4 slot in note
    const int grp   = lane >> 3;                      // which of warp's 4 notes
    const int gwarp = (blockIdx.x * blockDim.x + threadIdx.x) >> 5;
    const int note  = gwarp * 4 + grp;

    if (note >= N) return;

    const int a     = onset[note];
    const int b     = offset[note];
    const int len   = b - a;
    const float thr = 0.5f * (float)len;   // computed while loads are in flight

    float d;
    if (len == 32 && (a & 3) == 0) {
        // Fast path: one float4 per lane per track covers the segment.
        const float4 g = ((const float4*)(gen_f0 + a))[sub];
        const float4 t = ((const float4*)(t_f0  + a))[sub];
        d = ((g.x - t.x) + (g.y - t.y)) + ((g.z - t.z) + (g.w - t.w));
    } else {
        // General path: strided scalar loads over the segment.
        d = 0.0f;
        for (int i = a + sub; i < b; i += 8)
            d += gen_f0[i] - t_f0[i];
    }

    // Reduce within the 8-lane group (width = 8).
    #pragma unroll
    for (int o = 4; o > 0; o >>= 1)
        d += __shfl_down_sync(0xFFFFFFFFu, d, o, 8);

    // Group leader: predicated fire-and-forget reduction into the output.
    if (sub == 0 && fabsf(d) > thr)
        atomicAdd(out, inv_n);   // return unused -> REDG
}

extern "C" void kernel_launch(void* const* d_in, const int* in_sizes, int n_in,
                              void* d_out, int out_size) {
    const float* gen_f0 = (const float*)d_in[0];
    const float* t_f0   = (const float*)d_in[1];
    const int*   onset  = (const int*)d_in[2];
    const int*   offset = (const int*)d_in[3];
    float* out = (float*)d_out;

    const int N = in_sizes[2];            // number of notes (1024)
    const float inv_n = 1.0f / (float)N;  // fixed at graph capture

    // Zero the scalar output with a memset node (graph-capturable, async,
    // same stream -> ordered before the kernel's reductions).
    cudaMemsetAsync(out, 0, sizeof(float));

    const int THREADS = 256;                                  // 8 warps/block
    const int warps   = (N + 3) / 4;                          // 4 notes/warp
    const int blocks  = (warps * 32 + THREADS - 1) / THREADS; // 32
    pitch_loss_kernel<<<blocks, THREADS>>>(gen_f0, t_f0, onset, offset, out,
                                           N, inv_n);
}

// round 15
// speedup vs baseline: 1.2410x; 1.2410x over previous
#include <cuda_runtime.h>

// Pitch loss — final form (R8, the measured best: 6.21us total / 4.45us kernel).
//
// Structure: memset node zeroes the scalar output, then ONE retire-fast
// kernel. Grid 32 x 256 = 256 warps = 1024 eight-lane groups, one note each.
// Notes are contiguous 32-frame segments, so each lane issues ONE LDG.128 per
// track (warp covers 512B contiguous per track -> fully coalesced). Three
// width-8 shuffles reduce the gen-t difference; the group leader tests
// |sum| > 0.5*len (no division) and, only on a hit, issues a fire-and-forget
// float atomicAdd(out, 1/N). The unused return compiles to REDG (no-return
// reduction): no 318-cycle round trip, no completion tail, warps retire
// immediately. No __syncthreads, no device scratch, no in-kernel completion
// detection (measured across 6 variants: every completion scheme costs >=
// the node tax it would save, and weak-load polling is incorrect against
// L2-atomic-mutated state).
//
// Determinism: every contribution is exactly 2^-10 and all partial sums
// m/1024 (m <= 1024) are exactly representable in fp32, so the accumulation
// is order-independent and bit-exact across graph replays. d_out is zeroed
// by a memset node in the same stream (ordered before the kernel).
__global__ void __launch_bounds__(256, 1)
pitch_loss_kernel(const float* __restrict__ gen_f0,
                  const float* __restrict__ t_f0,
                  const int*   __restrict__ onset,
                  const int*   __restrict__ offset,
                  float*       __restrict__ out,
                  int N) {
    const int lane  = threadIdx.x & 31;
    const int sub   = lane & 7;                       // float4 slot in note
    const int grp   = lane >> 3;                      // which of warp's 4 notes
    const int gwarp = (blockIdx.x * blockDim.x + threadIdx.x) >> 5;
    const int note  = gwarp * 4 + grp;

    if (note >= N) return;

    const int a   = onset[note];
    const int b   = offset[note];
    const int len = b - a;

    float d;
    if (len == 32 && (a & 3) == 0) {
        // Fast path: one float4 per lane per track covers the segment.
        const float4 g = ((const float4*)(gen_f0 + a))[sub];
        const float4 t = ((const float4*)(t_f0  + a))[sub];
        d = ((g.x - t.x) + (g.y - t.y)) + ((g.z - t.z) + (g.w - t.w));
    } else {
        // General path: strided scalar loads over the segment.
        d = 0.0f;
        for (int i = a + sub; i < b; i += 8)
            d += gen_f0[i] - t_f0[i];
    }

    // Reduce within the 8-lane group (width = 8).
    #pragma unroll
    for (int o = 4; o > 0; o >>= 1)
        d += __shfl_down_sync(0xFFFFFFFFu, d, o, 8);

    // Group leader: predicated fire-and-forget reduction into the output.
    if (sub == 0 && fabsf(d) > 0.5f * (float)len)
        atomicAdd(out, 1.0f / (float)N);   // return unused -> REDG
}

extern "C" void kernel_launch(void* const* d_in, const int* in_sizes, int n_in,
                              void* d_out, int out_size) {
    const float* gen_f0 = (const float*)d_in[0];
    const float* t_f0   = (const float*)d_in[1];
    const int*   onset  = (const int*)d_in[2];
    const int*   offset = (const int*)d_in[3];
    float* out = (float*)d_out;

    const int N = in_sizes[2];   // number of notes (1024)

    // Zero the scalar output with a memset node (graph-capturable, async,
    // same stream -> ordered before the kernel's atomics).
    cudaMemsetAsync(out, 0, sizeof(float));

    const int THREADS = 256;                                  // 8 warps/block
    const int warps   = (N + 3) / 4;                          // 4 notes/warp
    const int blocks  = (warps * 32 + THREADS - 1) / THREADS; // 32
    pitch_loss_kernel<<<blocks, THREADS>>>(gen_f0, t_f0, onset, offset, out, N);
}